// round 15
// baseline (speedup 1.0000x reference)
#include <cuda_runtime.h>
#include <cuda_bf16.h>
#include <cstdint>

// Problem constants
#define NN 100000
#define EE 1600000
#define EPSV 1e-5f
#define SCAN_NB 98     // ceil(100000 / 1024)
#define EDGE_NB 6250   // prep_edges blocks

// ---------------------------------------------------------------------------
// Scratch (device globals; no runtime allocation allowed)
// ---------------------------------------------------------------------------
__device__ __align__(16) float g_H[(size_t)NN * 256];    // fp32 buffer A
__device__ __align__(16) float g_H2[(size_t)NN * 256];   // fp32 buffer B
__device__ __align__(16) float g_AGG[(size_t)NN * 256];  // fp32 buffer C
__device__ __align__(16) __nv_bfloat16 g_Ahi[(size_t)NN * 256]; // bf16 hi (layer-1 A)
__device__ __align__(16) __nv_bfloat16 g_Alo[(size_t)NN * 256]; // bf16 lo (layer-1 A)
__device__ __align__(16) __nv_bfloat16 g_Bhi[3][256 * 256];     // W^T hi per layer
__device__ __align__(16) __nv_bfloat16 g_Blo[3][256 * 256];     // W^T lo per layer
__device__ int   g_cnt[NN];      // in-degree (edges only)
__device__ int   g_off[NN + 1];  // CSR offsets (by dst)
__device__ int   g_rank[EE];     // per-edge rank within its dst bucket
__device__ int   g_blocksum[SCAN_NB];
__device__ __align__(8) int2 g_edge[EE];   // dst-sorted (src, norm-bits)
__device__ float g_sum1[256], g_sumsq1[256];   // layer-1 stats (gemm1 -> gemm2)
__device__ float g_sum2[256], g_sumsq2[256];   // layer-2 stats (gather2 -> gemm3)
__device__ float g_sum3[128], g_sumsq3[128];   // layer-3 stats (gather3 -> head)
__device__ int   g_is32;

// ---------------------------------------------------------------------------
// Helpers
// ---------------------------------------------------------------------------
__device__ __forceinline__ uint32_t smem_u32(const void* p) {
    uint32_t a;
    asm("{ .reg .u64 t; cvta.to.shared.u64 t, %1; cvt.u32.u64 %0, t; }" : "=r"(a) : "l"(p));
    return a;
}

__device__ __forceinline__ void cp16(uint32_t dst, const void* src, bool pred) {
    int sz = pred ? 16 : 0;
    asm volatile("cp.async.cg.shared.global [%0], [%1], 16, %2;"
                 :: "r"(dst), "l"(src), "r"(sz) : "memory");
}
__device__ __forceinline__ void cp_commit() {
    asm volatile("cp.async.commit_group;" ::: "memory");
}

#define LDSM_X4(r0, r1, r2, r3, addr) \
    asm volatile("ldmatrix.sync.aligned.m8n8.x4.shared.b16 {%0,%1,%2,%3}, [%4];" \
                 : "=r"(r0), "=r"(r1), "=r"(r2), "=r"(r3) : "r"(addr))

#define MMA16816(d, a, b) \
    asm volatile("mma.sync.aligned.m16n8k16.row.col.f32.bf16.bf16.f32 " \
                 "{%0,%1,%2,%3}, {%4,%5,%6,%7}, {%8,%9}, {%0,%1,%2,%3};" \
                 : "+f"((d)[0]), "+f"((d)[1]), "+f"((d)[2]), "+f"((d)[3]) \
                 : "r"((a)[0]), "r"((a)[1]), "r"((a)[2]), "r"((a)[3]), \
                   "r"((b)[0]), "r"((b)[1]))

__device__ __forceinline__ void decode_edge(const void* p, int e, int& s, int& d) {
    if (g_is32) {
        const int* q = (const int*)p;
        s = q[e]; d = q[EE + e];
    } else {
        const long long* q = (const long long*)p;
        s = (int)q[e]; d = (int)q[EE + e];
    }
}

// ---------------------------------------------------------------------------
// init: zero counts, zero ALL stats buffers, detect edge dtype
// ---------------------------------------------------------------------------
__global__ void init_kernel(const void* p) {
    int i = blockIdx.x * blockDim.x + threadIdx.x;
    if (i < NN) g_cnt[i] = 0;
    if (i < 256) {
        g_sum1[i] = 0.0f; g_sumsq1[i] = 0.0f;
        g_sum2[i] = 0.0f; g_sumsq2[i] = 0.0f;
        if (i < 128) { g_sum3[i] = 0.0f; g_sumsq3[i] = 0.0f; }
    }
    if (i == 0) {
        const long long* q = (const long long*)p;
        int bad = 0;
        for (int k = 0; k < 256; k++) {
            long long v = q[k];
            if (v < 0 || v >= NN) bad = 1;
        }
        g_is32 = bad;
    }
}

// ---------------------------------------------------------------------------
// prep_edges: count by dst, record per-edge rank (free from the atomic's
// return value). Folded weight prep in trailing blocks.
// ---------------------------------------------------------------------------
__global__ void prep_edges_kernel(const void* p,
                                  const float* __restrict__ W1,
                                  const float* __restrict__ W2,
                                  const float* __restrict__ W3) {
    int b = blockIdx.x;
    if (b < EDGE_NB) {
        int e = b * 256 + threadIdx.x;
        if (e >= EE) return;
        int s, d;
        decode_edge(p, e, s, d);
        g_rank[e] = atomicAdd(&g_cnt[d], 1);
    } else {
        int idx = (b - EDGE_NB) * 256 + threadIdx.x;  // 0..131071 exactly
        const float* W; int K, Nc, l;
        if (idx < 32768)       { W = W1; K = 128; Nc = 256; l = 0; }
        else if (idx < 98304)  { W = W2; K = 256; Nc = 256; l = 1; idx -= 32768; }
        else                   { W = W3; K = 256; Nc = 128; l = 2; idx -= 98304; }
        int k = idx / Nc, n = idx - k * Nc;
        float v = W[idx];
        __nv_bfloat16 h = __float2bfloat16(v);
        g_Bhi[l][n * K + k] = h;
        g_Blo[l][n * K + k] = __float2bfloat16(v - __bfloat162float(h));
    }
}

// Phase 1: per-block (1024 elems) exclusive scan -> g_off (local), total -> g_blocksum
__global__ void __launch_bounds__(1024) scan_local_kernel() {
    __shared__ int wsum[32];
    int tid = threadIdx.x, lane = tid & 31, w = tid >> 5;
    int i = blockIdx.x * 1024 + tid;
    int v = (i < NN) ? g_cnt[i] : 0;
    int x = v;
    #pragma unroll
    for (int o = 1; o < 32; o <<= 1) { int y = __shfl_up_sync(~0u, x, o); if (lane >= o) x += y; }
    if (lane == 31) wsum[w] = x;
    __syncthreads();
    if (w == 0) {
        int s = wsum[lane];
        #pragma unroll
        for (int o = 1; o < 32; o <<= 1) { int y = __shfl_up_sync(~0u, s, o); if (lane >= o) s += y; }
        wsum[lane] = s;
    }
    __syncthreads();
    int wpre = (w == 0) ? 0 : wsum[w - 1];
    if (i < NN) g_off[i] = wpre + (x - v);   // block-local exclusive scan
    if (tid == 1023) g_blocksum[blockIdx.x] = wpre + x;
}

// Phase 2+3 fused: each block computes its chunk's blocksum prefix inline,
// adds it, sets sentinel.
__global__ void __launch_bounds__(256) scan_add_kernel() {
    __shared__ int spre;
    const int tid = threadIdx.x, lane = tid & 31;
    const int chunk = blockIdx.x >> 2;  // 4 blocks of 256 per 1024-chunk
    if (tid < 32) {
        int s = 0;
        for (int j = lane; j < chunk; j += 32) s += g_blocksum[j];
        #pragma unroll
        for (int o = 16; o; o >>= 1) s += __shfl_xor_sync(~0u, s, o);
        if (lane == 0) spre = s;
    }
    __syncthreads();
    int i = blockIdx.x * 256 + tid;
    if (i < NN) g_off[i] += spre;
    if (i == 0) g_off[NN] = EE;
}

// Atomic-free fill: pos = off[d] + rank[e]; src/dst re-decoded from input.
__global__ void fill_kernel(const void* p) {
    int e = blockIdx.x * blockDim.x + threadIdx.x;
    if (e >= EE) return;
    int s, d;
    decode_edge(p, e, s, d);
    int pos = g_off[d] + g_rank[e];
    float nrm = rsqrtf((float)(g_cnt[s] + 1)) * rsqrtf((float)(g_cnt[d] + 1));
    g_edge[pos] = make_int2(s, __float_as_int(nrm));
}

// ---------------------------------------------------------------------------
// CSR gather-aggregate: one warp per node, NV=D/128 float4 vectors per lane;
// 8-edge unroll when NV==1, 4-edge otherwise. int2 edge metadata.
// EMIT_BF: write bf16 hi/lo instead of fp32 (layer-1 A operand).
// STATS:   per-column sum/sumsq into pS/pQ (block-reduce + atomicAdd).
// ---------------------------------------------------------------------------
template <int D, bool EMIT_BF, bool STATS>
__global__ void __launch_bounds__(256) gather_agg_kernel(
    const float* __restrict__ H, float* __restrict__ OUT,
    __nv_bfloat16* __restrict__ Ohi, __nv_bfloat16* __restrict__ Olo,
    float* __restrict__ pS, float* __restrict__ pQ) {
    __shared__ float sS[D], sQ[D];
    const int NV = D / 128;
    const int tid = threadIdx.x;
    const int w = tid >> 5, lane = tid & 31;
    if (STATS) {
        if (tid < D) { sS[tid] = 0.0f; sQ[tid] = 0.0f; }
        __syncthreads();
    }
    float stS[NV][4], stQ[NV][4];
    #pragma unroll
    for (int v = 0; v < NV; v++)
        #pragma unroll
        for (int q = 0; q < 4; q++) { stS[v][q] = 0.0f; stQ[v][q] = 0.0f; }
    const int2* __restrict__ E = g_edge;

    for (int node = blockIdx.x * 8 + w; node < NN; node += gridDim.x * 8) {
        float4 acc[NV];
        float selfw = 1.0f / (float)(g_cnt[node] + 1);
        #pragma unroll
        for (int v = 0; v < NV; v++) {
            float4 h = ((const float4*)(H + (size_t)node * D))[lane + 32 * v];
            acc[v] = make_float4(h.x * selfw, h.y * selfw, h.z * selfw, h.w * selfw);
        }
        int j = g_off[node], jend = g_off[node + 1];
        if (NV == 1) {
            for (; j + 8 <= jend; j += 8) {
                int2 m[8];
                #pragma unroll
                for (int k = 0; k < 8; k++) m[k] = E[j + k];
                float4 h[8];
                #pragma unroll
                for (int k = 0; k < 8; k++)
                    h[k] = ((const float4*)(H + (size_t)m[k].x * D))[lane];
                #pragma unroll
                for (int k = 0; k < 8; k++) {
                    float wt = __int_as_float(m[k].y);
                    acc[0].x += wt * h[k].x; acc[0].y += wt * h[k].y;
                    acc[0].z += wt * h[k].z; acc[0].w += wt * h[k].w;
                }
            }
        }
        for (; j + 4 <= jend; j += 4) {
            int2 m0 = E[j], m1 = E[j + 1], m2 = E[j + 2], m3 = E[j + 3];
            float w0 = __int_as_float(m0.y), w1 = __int_as_float(m1.y);
            float w2 = __int_as_float(m2.y), w3 = __int_as_float(m3.y);
            #pragma unroll
            for (int v = 0; v < NV; v++) {
                float4 h0 = ((const float4*)(H + (size_t)m0.x * D))[lane + 32 * v];
                float4 h1 = ((const float4*)(H + (size_t)m1.x * D))[lane + 32 * v];
                float4 h2 = ((const float4*)(H + (size_t)m2.x * D))[lane + 32 * v];
                float4 h3 = ((const float4*)(H + (size_t)m3.x * D))[lane + 32 * v];
                acc[v].x += w0 * h0.x + w1 * h1.x + w2 * h2.x + w3 * h3.x;
                acc[v].y += w0 * h0.y + w1 * h1.y + w2 * h2.y + w3 * h3.y;
                acc[v].z += w0 * h0.z + w1 * h1.z + w2 * h2.z + w3 * h3.z;
                acc[v].w += w0 * h0.w + w1 * h1.w + w2 * h2.w + w3 * h3.w;
            }
        }
        for (; j < jend; j++) {
            int2 m = E[j];
            float wt = __int_as_float(m.y);
            #pragma unroll
            for (int v = 0; v < NV; v++) {
                float4 h = ((const float4*)(H + (size_t)m.x * D))[lane + 32 * v];
                acc[v].x += wt * h.x; acc[v].y += wt * h.y;
                acc[v].z += wt * h.z; acc[v].w += wt * h.w;
            }
        }
        #pragma unroll
        for (int v = 0; v < NV; v++) {
            if (EMIT_BF) {
                union { __nv_bfloat16 bb[4]; uint2 u; } Hh, Ll;
                #pragma unroll
                for (int q = 0; q < 4; q++) {
                    float val = (&acc[v].x)[q];
                    Hh.bb[q] = __float2bfloat16(val);
                    Ll.bb[q] = __float2bfloat16(val - __bfloat162float(Hh.bb[q]));
                }
                ((uint2*)(Ohi + (size_t)node * D))[lane + 32 * v] = Hh.u;
                ((uint2*)(Olo + (size_t)node * D))[lane + 32 * v] = Ll.u;
            } else {
                ((float4*)(OUT + (size_t)node * D))[lane + 32 * v] = acc[v];
            }
            if (STATS) {
                #pragma unroll
                for (int q = 0; q < 4; q++) {
                    float val = (&acc[v].x)[q];
                    stS[v][q] += val;
                    stQ[v][q] += val * val;
                }
            }
        }
    }
    if (STATS) {
        #pragma unroll
        for (int v = 0; v < NV; v++)
            #pragma unroll
            for (int q = 0; q < 4; q++) {
                atomicAdd(&sS[4 * lane + 128 * v + q], stS[v][q]);
                atomicAdd(&sQ[4 * lane + 128 * v + q], stQ[v][q]);
            }
        __syncthreads();
        for (int i = tid; i < D; i += 256) {
            atomicAdd(&pS[i], sS[i]);
            atomicAdd(&pQ[i], sQ[i]);
        }
    }
}

// ---------------------------------------------------------------------------
// HMMA bf16 hi/lo split GEMM, pass-fused: C = A @ W.
// CTA 128x128, 256 thr (2Mx4N warps, warp tile 64x32), 2-stage double buffer,
// TWO CTAs per SM. Per K-chunk(32): Ahi*Bhi + Alo*Bhi + Ahi*Blo.
// BNLOAD: A loaded as fp32 + BN(pSin/pQin)+ReLU+hi/lo split in the loader.
// STATS:  fused per-column sum/sumsq of C into pSout/pQout (layer 1).
// ---------------------------------------------------------------------------
#define PAD 40
#define TILE_B (128 * PAD * 2)          // 10240 B per tile (bf16)
#define STAGE_B (4 * TILE_B)            // Ahi,Alo,Bhi,Blo = 40960
#define GEMM_SMEM (2 * STAGE_B)         // 81920 B -> 2 CTAs/SM

template <int K, bool STATS, bool BNLOAD>
__global__ void __launch_bounds__(256, 2) mma_gemm_kernel(
    const __nv_bfloat16* __restrict__ Ahi, const __nv_bfloat16* __restrict__ Alo,
    const float* __restrict__ Afp, const float* __restrict__ gamma,
    const float* __restrict__ beta,
    const float* __restrict__ pSin, const float* __restrict__ pQin,
    float* __restrict__ pSout, float* __restrict__ pQout,
    const __nv_bfloat16* __restrict__ Bhi, const __nv_bfloat16* __restrict__ Blo,
    float* __restrict__ C, int Nc) {
    extern __shared__ char smem[];
    __shared__ float sS[128], sQ[128];
    __shared__ float sMuA[256], sScA[256], sBeA[256];
    const uint32_t sbase = smem_u32(smem);

    const int tid = threadIdx.x;
    const int warp = tid >> 5, lane = tid & 31;
    const int wm = warp >> 2, wn = warp & 3;  // 2x4 warps, warp tile 64x32
    const int m0 = blockIdx.y * 128;
    const int n0 = blockIdx.x * 128;

    if (STATS && tid < 128) { sS[tid] = 0.0f; sQ[tid] = 0.0f; }
    if (BNLOAD) {
        const float invn = 1.0f / (float)NN;
        for (int i = tid; i < K; i += 256) {
            float mu = pSin[i] * invn;
            float var = pQin[i] * invn - mu * mu;
            sMuA[i] = mu;
            sScA[i] = gamma[i] * rsqrtf(var + EPSV);
            sBeA[i] = beta[i];
        }
        __syncthreads();
    }

    float acc[4][4][4];
    #pragma unroll
    for (int i = 0; i < 4; i++)
        #pragma unroll
        for (int j = 0; j < 4; j++)
            #pragma unroll
            for (int q = 0; q < 4; q++) acc[i][j][q] = 0.0f;

    const int KC = K / 32;
    const int lrow = tid >> 2;   // 0..63 (rows lrow, lrow+64)
    const int lseg = tid & 3;

    auto issue = [&](int c) {
        const int p = c & 1;
        const int col0 = c * 32 + lseg * 8;
        #pragma unroll
        for (int h = 0; h < 2; h++) {
            int row = lrow + h * 64;
            const uint32_t off = (uint32_t)(p * STAGE_B) + (uint32_t)(row * PAD + lseg * 8) * 2;
            const uint32_t sb = sbase + off;
            int ra = m0 + row;
            bool ok = ra < NN;
            int rc = ok ? ra : 0;
            if (BNLOAD) {
                const float4* src = (const float4*)(Afp + (size_t)rc * K + col0);
                float4 v0 = src[0], v1 = src[1];
                float vv[8] = {v0.x, v0.y, v0.z, v0.w, v1.x, v1.y, v1.z, v1.w};
                union { __nv_bfloat16 b[8]; uint4 u; } Hh, Ll;
                #pragma unroll
                for (int q = 0; q < 8; q++) {
                    int cc = col0 + q;
                    float v = (vv[q] - sMuA[cc]) * sScA[cc] + sBeA[cc];
                    v = v > 0.0f ? v : 0.0f;
                    if (!ok) v = 0.0f;
                    Hh.b[q] = __float2bfloat16(v);
                    Ll.b[q] = __float2bfloat16(v - __bfloat162float(Hh.b[q]));
                }
                *(uint4*)(smem + off + 0 * TILE_B) = Hh.u;
                *(uint4*)(smem + off + 1 * TILE_B) = Ll.u;
            } else {
                cp16(sb + 0 * TILE_B, Ahi + (size_t)rc * K + col0, ok);
                cp16(sb + 1 * TILE_B, Alo + (size_t)rc * K + col0, ok);
            }
            cp16(sb + 2 * TILE_B, Bhi + (size_t)(n0 + row) * K + col0, true);
            cp16(sb + 3 * TILE_B, Blo + (size_t)(n0 + row) * K + col0, true);
        }
        cp_commit();
    };

    issue(0);
    if (KC > 1) issue(1); else cp_commit();

    const int jj = lane >> 3, rr = lane & 7;

    for (int c = 0; c < KC; c++) {
        if (c + 1 < KC) asm volatile("cp.async.wait_group 1;" ::: "memory");
        else            asm volatile("cp.async.wait_group 0;" ::: "memory");
        __syncthreads();   // stage c (cp.async + STS) visible to all warps

        const int p = c & 1;
        const uint32_t st = sbase + (uint32_t)(p * STAGE_B);

        #pragma unroll
        for (int ks = 0; ks < 2; ks++) {
            const int acol = ks * 16 + (jj >> 1) * 8;
            const int bcol = ks * 16 + (jj & 1) * 8;
            uint32_t ahi[4][4], alo[4][4], bhi[4][2];
            #pragma unroll
            for (int i = 0; i < 4; i++) {
                int row = wm * 64 + i * 16 + (jj & 1) * 8 + rr;
                uint32_t off = (uint32_t)(row * PAD + acol) * 2;
                LDSM_X4(ahi[i][0], ahi[i][1], ahi[i][2], ahi[i][3], st + 0 * TILE_B + off);
                LDSM_X4(alo[i][0], alo[i][1], alo[i][2], alo[i][3], st + 1 * TILE_B + off);
            }
            #pragma unroll
            for (int jt = 0; jt < 2; jt++) {
                int nrow = wn * 32 + jt * 16 + (jj >> 1) * 8 + rr;
                uint32_t off = (uint32_t)(nrow * PAD + bcol) * 2;
                LDSM_X4(bhi[jt * 2][0], bhi[jt * 2][1], bhi[jt * 2 + 1][0], bhi[jt * 2 + 1][1],
                        st + 2 * TILE_B + off);
            }
            #pragma unroll
            for (int i = 0; i < 4; i++)
                #pragma unroll
                for (int j = 0; j < 4; j++) {
                    MMA16816(acc[i][j], ahi[i], bhi[j]);
                    MMA16816(acc[i][j], alo[i], bhi[j]);
                }
            uint32_t blo[4][2];
            #pragma unroll
            for (int jt = 0; jt < 2; jt++) {
                int nrow = wn * 32 + jt * 16 + (jj >> 1) * 8 + rr;
                uint32_t off = (uint32_t)(nrow * PAD + bcol) * 2;
                LDSM_X4(blo[jt * 2][0], blo[jt * 2][1], blo[jt * 2 + 1][0], blo[jt * 2 + 1][1],
                        st + 3 * TILE_B + off);
            }
            #pragma unroll
            for (int i = 0; i < 4; i++)
                #pragma unroll
                for (int j = 0; j < 4; j++)
                    MMA16816(acc[i][j], ahi[i], blo[j]);
        }
        __syncthreads();   // all warps done with stage c before refill
        if (c + 2 < KC) issue(c + 2);
    }

    // Epilogue: C writes
    const int g = lane >> 2, t2 = (lane & 3) * 2;
    #pragma unroll
    for (int i = 0; i < 4; i++) {
        int row0 = m0 + wm * 64 + i * 16 + g;
        #pragma unroll
        for (int j = 0; j < 4; j++) {
            int col = n0 + wn * 32 + j * 8 + t2;
            if (row0 < NN)
                *(float2*)(C + (size_t)row0 * Nc + col) = make_float2(acc[i][j][0], acc[i][j][1]);
            if (row0 + 8 < NN)
                *(float2*)(C + (size_t)(row0 + 8) * Nc + col) = make_float2(acc[i][j][2], acc[i][j][3]);
        }
    }

    if (STATS) {
        // rows beyond NN were zero-filled in A -> contribute 0; no guard needed
        #pragma unroll
        for (int j = 0; j < 4; j++)
            #pragma unroll
            for (int qq = 0; qq < 2; qq++) {
                float s = 0.0f, q2 = 0.0f;
                #pragma unroll
                for (int i = 0; i < 4; i++) {
                    float a0 = acc[i][j][qq], a1 = acc[i][j][qq + 2];
                    s += a0 + a1;
                    q2 += a0 * a0 + a1 * a1;
                }
                #pragma unroll
                for (int off = 4; off < 32; off <<= 1) {
                    s  += __shfl_xor_sync(~0u, s, off);
                    q2 += __shfl_xor_sync(~0u, q2, off);
                }
                if (lane < 4) {
                    int col = wn * 32 + j * 8 + lane * 2 + qq;
                    atomicAdd(&sS[col], s);
                    atomicAdd(&sQ[col], q2);
                }
            }
        __syncthreads();
        if (tid < 128) {
            atomicAdd(&pSout[n0 + tid], sS[tid]);
            atomicAdd(&pQout[n0 + tid], sQ[tid]);
        }
    }
}

// ---------------------------------------------------------------------------
// Fused layer-3 BN+ReLU + head: OUT[N,10] = relu(BN(X)) @ Wout + bout.
// ---------------------------------------------------------------------------
__global__ void __launch_bounds__(256) bn_head_kernel(
    const float* __restrict__ X, const float* __restrict__ gamma,
    const float* __restrict__ beta, const float* __restrict__ W,
    const float* __restrict__ bias, float* __restrict__ OUT) {
    __shared__ float sW[128 * 10];
    __shared__ float sb[10];
    __shared__ float sMu[128], sSc[128], sBe[128];
    int tid = threadIdx.x;
    for (int i = tid; i < 1280; i += 256) sW[i] = W[i];
    if (tid < 10) sb[tid] = bias[tid];
    if (tid < 128) {
        const float invn = 1.0f / (float)NN;
        float mu = g_sum3[tid] * invn;
        float var = g_sumsq3[tid] * invn - mu * mu;
        sMu[tid] = mu;
        sSc[tid] = gamma[tid] * rsqrtf(var + EPSV);
        sBe[tid] = beta[tid];
    }
    __syncthreads();
    int warp = tid >> 5, lane = tid & 31;
    int row = blockIdx.x * 8 + warp;
    if (row >= NN) return;
    float4 x = *(const float4*)(X + (size_t)row * 128 + lane * 4);
    float y[4];
    #pragma unroll
    for (int q = 0; q < 4; q++) {
        int c = lane * 4 + q;
        float v = ((&x.x)[q] - sMu[c]) * sSc[c] + sBe[c];
        y[q] = v > 0.0f ? v : 0.0f;
    }
    #pragma unroll
    for (int c = 0; c < 10; c++) {
        float p = y[0] * sW[(lane * 4 + 0) * 10 + c] + y[1] * sW[(lane * 4 + 1) * 10 + c] +
                  y[2] * sW[(lane * 4 + 2) * 10 + c] + y[3] * sW[(lane * 4 + 3) * 10 + c];
        #pragma unroll
        for (int off = 16; off; off >>= 1) p += __shfl_xor_sync(0xffffffffu, p, off);
        if (lane == 0) OUT[(size_t)row * 10 + c] = p + sb[c];
    }
}

// ---------------------------------------------------------------------------
// Host-side orchestration
// ---------------------------------------------------------------------------
template <typename T>
static inline T* sym_addr(const void* sym) {
    void* p = nullptr;
    cudaGetSymbolAddress(&p, sym);
    return (T*)p;
}

extern "C" void kernel_launch(void* const* d_in, const int* in_sizes, int n_in,
                              void* d_out, int out_size) {
    const float* x   = (const float*)d_in[0];
    const void*  ei  = d_in[1];
    const float* W1  = (const float*)d_in[2];
    const float* g1  = (const float*)d_in[4];
    const float* be1 = (const float*)d_in[5];
    const float* W2  = (const float*)d_in[6];
    const float* g2  = (const float*)d_in[8];
    const float* be2 = (const float*)d_in[9];
    const float* W3  = (const float*)d_in[10];
    const float* g3  = (const float*)d_in[12];
    const float* be3 = (const float*)d_in[13];
    const float* Wo  = (const float*)d_in[14];
    const float* bo  = (const float*)d_in[15];
    float* out = (float*)d_out;

    float* H   = sym_addr<float>(g_H);
    float* H2  = sym_addr<float>(g_H2);
    float* AGG = sym_addr<float>(g_AGG);
    __nv_bfloat16* Ahi = sym_addr<__nv_bfloat16>(g_Ahi);
    __nv_bfloat16* Alo = sym_addr<__nv_bfloat16>(g_Alo);
    __nv_bfloat16* Bhi = sym_addr<__nv_bfloat16>(g_Bhi);
    __nv_bfloat16* Blo = sym_addr<__nv_bfloat16>(g_Blo);
    float* s1 = sym_addr<float>(g_sum1);
    float* q1 = sym_addr<float>(g_sumsq1);
    float* s2 = sym_addr<float>(g_sum2);
    float* q2 = sym_addr<float>(g_sumsq2);
    float* s3 = sym_addr<float>(g_sum3);
    float* q3 = sym_addr<float>(g_sumsq3);

    static int smem_set = 0;
    if (!smem_set) {
        cudaFuncSetAttribute(mma_gemm_kernel<128, true, false>, cudaFuncAttributeMaxDynamicSharedMemorySize, GEMM_SMEM);
        cudaFuncSetAttribute(mma_gemm_kernel<256, false, true>, cudaFuncAttributeMaxDynamicSharedMemorySize, GEMM_SMEM);
        smem_set = 1;
    }

    const int TB = 256;
    const int MT = (NN + 127) / 128;  // 782 M-tiles
    const int GAB = 1184;             // gather blocks (148 SMs x 8)

    // ---- graph prep: CSR by dst (rank-based, atomic-free fill) ----
    init_kernel<<<(NN + TB - 1) / TB, TB>>>(ei);
    prep_edges_kernel<<<EDGE_NB + 512, TB>>>(ei, W1, W2, W3);  // + folded weight prep
    scan_local_kernel<<<SCAN_NB, 1024>>>();
    scan_add_kernel<<<(NN + TB - 1) / TB, TB>>>();             // tops prefix inline
    fill_kernel<<<(EE + TB - 1) / TB, TB>>>(ei);

    // ---- layer 1: aggregate x (128, emit bf16) -> GEMM(+stats1) -> H ----
    gather_agg_kernel<128, true, false><<<GAB, 256>>>(x, nullptr, Ahi, Alo, nullptr, nullptr);
    mma_gemm_kernel<128, true, false><<<dim3(2, MT), 256, GEMM_SMEM>>>(
        Ahi, Alo, nullptr, nullptr, nullptr, nullptr, nullptr, s1, q1,
        Bhi + 0 * 65536, Blo + 0 * 65536, H, 256);

    // ---- layer 2: GEMM(BN1(H) fused) -> H2; gather(+stats2) -> AGG ----
    mma_gemm_kernel<256, false, true><<<dim3(2, MT), 256, GEMM_SMEM>>>(
        nullptr, nullptr, H, g1, be1, s1, q1, nullptr, nullptr,
        Bhi + 1 * 65536, Blo + 1 * 65536, H2, 256);
    gather_agg_kernel<256, false, true><<<GAB, 256>>>(H2, AGG, nullptr, nullptr, s2, q2);

    // ---- layer 3: GEMM(BN2(AGG) fused) -> H (128); gather(+stats3) -> H2 ----
    mma_gemm_kernel<256, false, true><<<dim3(1, MT), 256, GEMM_SMEM>>>(
        nullptr, nullptr, AGG, g2, be2, s2, q2, nullptr, nullptr,
        Bhi + 2 * 65536, Blo + 2 * 65536, H, 128);
    gather_agg_kernel<128, false, true><<<GAB, 256>>>(H, H2, nullptr, nullptr, s3, q3);

    // ---- head: relu(BN3(H2)) @ Wout + bout ----
    bn_head_kernel<<<(NN + 7) / 8, 256>>>(H2, g3, be3, Wo, bo, out);
}

// round 16
// speedup vs baseline: 1.4001x; 1.4001x over previous
#include <cuda_runtime.h>
#include <cuda_bf16.h>
#include <cstdint>

// Problem constants
#define NN 100000
#define EE 1600000
#define EPSV 1e-5f
#define SCAN_NB 98     // ceil(100000 / 1024)
#define EDGE_NB 6250   // prep_edges blocks

// ---------------------------------------------------------------------------
// Scratch (device globals; no runtime allocation allowed)
// ---------------------------------------------------------------------------
__device__ __align__(16) float g_H[(size_t)NN * 256];    // fp32 buffer A
__device__ __align__(16) float g_H2[(size_t)NN * 256];   // fp32 buffer B
__device__ __align__(16) float g_AGG[(size_t)NN * 256];  // fp32 buffer C
__device__ __align__(16) __nv_bfloat16 g_Ahi[(size_t)NN * 256]; // bf16 hi (layer-1 A)
__device__ __align__(16) __nv_bfloat16 g_Alo[(size_t)NN * 256]; // bf16 lo (layer-1 A)
__device__ __align__(16) __nv_bfloat16 g_Bhi[3][256 * 256];     // W^T hi per layer
__device__ __align__(16) __nv_bfloat16 g_Blo[3][256 * 256];     // W^T lo per layer
__device__ int   g_cnt[NN];      // in-degree (edges only)
__device__ int   g_off[NN + 1];  // CSR offsets (by dst)
__device__ int   g_cur[NN];      // fill cursors
__device__ int   g_blocksum[SCAN_NB];
__device__ int   g_src[EE];
__device__ int   g_dst[EE];
__device__ __align__(8) int2 g_edge[EE];   // dst-sorted (src, norm-bits)
__device__ float g_sum1[256], g_sumsq1[256];   // layer-1 stats (gemm1 -> gemm2)
__device__ float g_sum2[256], g_sumsq2[256];   // layer-2 stats (gather2 -> gemm3)
__device__ float g_sum3[128], g_sumsq3[128];   // layer-3 stats (gather3 -> head)
__device__ int   g_is32;

// ---------------------------------------------------------------------------
// Helpers
// ---------------------------------------------------------------------------
__device__ __forceinline__ uint32_t smem_u32(const void* p) {
    uint32_t a;
    asm("{ .reg .u64 t; cvta.to.shared.u64 t, %1; cvt.u32.u64 %0, t; }" : "=r"(a) : "l"(p));
    return a;
}

__device__ __forceinline__ void cp16(uint32_t dst, const void* src, bool pred) {
    int sz = pred ? 16 : 0;
    asm volatile("cp.async.cg.shared.global [%0], [%1], 16, %2;"
                 :: "r"(dst), "l"(src), "r"(sz) : "memory");
}
__device__ __forceinline__ void cp_commit() {
    asm volatile("cp.async.commit_group;" ::: "memory");
}

#define LDSM_X4(r0, r1, r2, r3, addr) \
    asm volatile("ldmatrix.sync.aligned.m8n8.x4.shared.b16 {%0,%1,%2,%3}, [%4];" \
                 : "=r"(r0), "=r"(r1), "=r"(r2), "=r"(r3) : "r"(addr))

#define MMA16816(d, a, b) \
    asm volatile("mma.sync.aligned.m16n8k16.row.col.f32.bf16.bf16.f32 " \
                 "{%0,%1,%2,%3}, {%4,%5,%6,%7}, {%8,%9}, {%0,%1,%2,%3};" \
                 : "+f"((d)[0]), "+f"((d)[1]), "+f"((d)[2]), "+f"((d)[3]) \
                 : "r"((a)[0]), "r"((a)[1]), "r"((a)[2]), "r"((a)[3]), \
                   "r"((b)[0]), "r"((b)[1]))

// ---------------------------------------------------------------------------
// init: zero counts, zero ALL stats buffers, detect edge dtype
// ---------------------------------------------------------------------------
__global__ void init_kernel(const void* p) {
    int i = blockIdx.x * blockDim.x + threadIdx.x;
    if (i < NN) g_cnt[i] = 0;
    if (i < 256) {
        g_sum1[i] = 0.0f; g_sumsq1[i] = 0.0f;
        g_sum2[i] = 0.0f; g_sumsq2[i] = 0.0f;
        if (i < 128) { g_sum3[i] = 0.0f; g_sumsq3[i] = 0.0f; }
    }
    if (i == 0) {
        const long long* q = (const long long*)p;
        int bad = 0;
        for (int k = 0; k < 256; k++) {
            long long v = q[k];
            if (v < 0 || v >= NN) bad = 1;
        }
        g_is32 = bad;
    }
}

// ---------------------------------------------------------------------------
// prep_edges (+ folded weight prep in trailing blocks).
// NOTE: atomic result is DISCARDED -> compiles to REDG (fire-and-forget).
// ---------------------------------------------------------------------------
__global__ void prep_edges_kernel(const void* p,
                                  const float* __restrict__ W1,
                                  const float* __restrict__ W2,
                                  const float* __restrict__ W3) {
    int b = blockIdx.x;
    if (b < EDGE_NB) {
        int e = b * 256 + threadIdx.x;
        if (e >= EE) return;
        int s, d;
        if (g_is32) {
            const int* q = (const int*)p;
            s = q[e]; d = q[EE + e];
        } else {
            const long long* q = (const long long*)p;
            s = (int)q[e]; d = (int)q[EE + e];
        }
        g_src[e] = s;
        g_dst[e] = d;
        atomicAdd(&g_cnt[d], 1);
    } else {
        int idx = (b - EDGE_NB) * 256 + threadIdx.x;  // 0..131071 exactly
        const float* W; int K, Nc, l;
        if (idx < 32768)       { W = W1; K = 128; Nc = 256; l = 0; }
        else if (idx < 98304)  { W = W2; K = 256; Nc = 256; l = 1; idx -= 32768; }
        else                   { W = W3; K = 256; Nc = 128; l = 2; idx -= 98304; }
        int k = idx / Nc, n = idx - k * Nc;
        float v = W[idx];
        __nv_bfloat16 h = __float2bfloat16(v);
        g_Bhi[l][n * K + k] = h;
        g_Blo[l][n * K + k] = __float2bfloat16(v - __bfloat162float(h));
    }
}

// Phase 1: per-block (1024 elems) exclusive scan -> g_off (local), total -> g_blocksum
__global__ void __launch_bounds__(1024) scan_local_kernel() {
    __shared__ int wsum[32];
    int tid = threadIdx.x, lane = tid & 31, w = tid >> 5;
    int i = blockIdx.x * 1024 + tid;
    int v = (i < NN) ? g_cnt[i] : 0;
    int x = v;
    #pragma unroll
    for (int o = 1; o < 32; o <<= 1) { int y = __shfl_up_sync(~0u, x, o); if (lane >= o) x += y; }
    if (lane == 31) wsum[w] = x;
    __syncthreads();
    if (w == 0) {
        int s = wsum[lane];
        #pragma unroll
        for (int o = 1; o < 32; o <<= 1) { int y = __shfl_up_sync(~0u, s, o); if (lane >= o) s += y; }
        wsum[lane] = s;
    }
    __syncthreads();
    int wpre = (w == 0) ? 0 : wsum[w - 1];
    if (i < NN) g_off[i] = wpre + (x - v);   // block-local exclusive scan
    if (tid == 1023) g_blocksum[blockIdx.x] = wpre + x;
}

// Phase 2+3 fused: each block computes its chunk's blocksum prefix inline,
// adds it, inits cursors, sets sentinel.
__global__ void __launch_bounds__(256) scan_add_kernel() {
    __shared__ int spre;
    const int tid = threadIdx.x, lane = tid & 31;
    const int chunk = blockIdx.x >> 2;  // 4 blocks of 256 per 1024-chunk
    if (tid < 32) {
        int s = 0;
        for (int j = lane; j < chunk; j += 32) s += g_blocksum[j];
        #pragma unroll
        for (int o = 16; o; o >>= 1) s += __shfl_xor_sync(~0u, s, o);
        if (lane == 0) spre = s;
    }
    __syncthreads();
    int i = blockIdx.x * 256 + tid;
    if (i < NN) {
        int o = g_off[i] + spre;
        g_off[i] = o;
        g_cur[i] = o;
    }
    if (i == 0) g_off[NN] = EE;
}

__global__ void fill_kernel() {
    int e = blockIdx.x * blockDim.x + threadIdx.x;
    if (e >= EE) return;
    int s = g_src[e], d = g_dst[e];
    int pos = atomicAdd(&g_cur[d], 1);
    float nrm = rsqrtf((float)(g_cnt[s] + 1)) * rsqrtf((float)(g_cnt[d] + 1));
    g_edge[pos] = make_int2(s, __float_as_int(nrm));
}

// ---------------------------------------------------------------------------
// CSR gather-aggregate: one warp per node, NV=D/128 float4 vectors per lane;
// 8-edge unroll when NV==1, 4-edge otherwise. int2 edge metadata.
// EMIT_BF: write bf16 hi/lo instead of fp32 (layer-1 A operand).
// STATS:   per-column sum/sumsq into pS/pQ (block-reduce + atomicAdd).
// ---------------------------------------------------------------------------
template <int D, bool EMIT_BF, bool STATS>
__global__ void __launch_bounds__(256) gather_agg_kernel(
    const float* __restrict__ H, float* __restrict__ OUT,
    __nv_bfloat16* __restrict__ Ohi, __nv_bfloat16* __restrict__ Olo,
    float* __restrict__ pS, float* __restrict__ pQ) {
    __shared__ float sS[D], sQ[D];
    const int NV = D / 128;
    const int tid = threadIdx.x;
    const int w = tid >> 5, lane = tid & 31;
    if (STATS) {
        if (tid < D) { sS[tid] = 0.0f; sQ[tid] = 0.0f; }
        __syncthreads();
    }
    float stS[NV][4], stQ[NV][4];
    #pragma unroll
    for (int v = 0; v < NV; v++)
        #pragma unroll
        for (int q = 0; q < 4; q++) { stS[v][q] = 0.0f; stQ[v][q] = 0.0f; }
    const int2* __restrict__ E = g_edge;

    for (int node = blockIdx.x * 8 + w; node < NN; node += gridDim.x * 8) {
        float4 acc[NV];
        float selfw = 1.0f / (float)(g_cnt[node] + 1);
        #pragma unroll
        for (int v = 0; v < NV; v++) {
            float4 h = ((const float4*)(H + (size_t)node * D))[lane + 32 * v];
            acc[v] = make_float4(h.x * selfw, h.y * selfw, h.z * selfw, h.w * selfw);
        }
        int j = g_off[node], jend = g_off[node + 1];
        if (NV == 1) {
            for (; j + 8 <= jend; j += 8) {
                int2 m[8];
                #pragma unroll
                for (int k = 0; k < 8; k++) m[k] = E[j + k];
                float4 h[8];
                #pragma unroll
                for (int k = 0; k < 8; k++)
                    h[k] = ((const float4*)(H + (size_t)m[k].x * D))[lane];
                #pragma unroll
                for (int k = 0; k < 8; k++) {
                    float wt = __int_as_float(m[k].y);
                    acc[0].x += wt * h[k].x; acc[0].y += wt * h[k].y;
                    acc[0].z += wt * h[k].z; acc[0].w += wt * h[k].w;
                }
            }
        }
        for (; j + 4 <= jend; j += 4) {
            int2 m0 = E[j], m1 = E[j + 1], m2 = E[j + 2], m3 = E[j + 3];
            float w0 = __int_as_float(m0.y), w1 = __int_as_float(m1.y);
            float w2 = __int_as_float(m2.y), w3 = __int_as_float(m3.y);
            #pragma unroll
            for (int v = 0; v < NV; v++) {
                float4 h0 = ((const float4*)(H + (size_t)m0.x * D))[lane + 32 * v];
                float4 h1 = ((const float4*)(H + (size_t)m1.x * D))[lane + 32 * v];
                float4 h2 = ((const float4*)(H + (size_t)m2.x * D))[lane + 32 * v];
                float4 h3 = ((const float4*)(H + (size_t)m3.x * D))[lane + 32 * v];
                acc[v].x += w0 * h0.x + w1 * h1.x + w2 * h2.x + w3 * h3.x;
                acc[v].y += w0 * h0.y + w1 * h1.y + w2 * h2.y + w3 * h3.y;
                acc[v].z += w0 * h0.z + w1 * h1.z + w2 * h2.z + w3 * h3.z;
                acc[v].w += w0 * h0.w + w1 * h1.w + w2 * h2.w + w3 * h3.w;
            }
        }
        for (; j < jend; j++) {
            int2 m = E[j];
            float wt = __int_as_float(m.y);
            #pragma unroll
            for (int v = 0; v < NV; v++) {
                float4 h = ((const float4*)(H + (size_t)m.x * D))[lane + 32 * v];
                acc[v].x += wt * h.x; acc[v].y += wt * h.y;
                acc[v].z += wt * h.z; acc[v].w += wt * h.w;
            }
        }
        #pragma unroll
        for (int v = 0; v < NV; v++) {
            if (EMIT_BF) {
                union { __nv_bfloat16 bb[4]; uint2 u; } Hh, Ll;
                #pragma unroll
                for (int q = 0; q < 4; q++) {
                    float val = (&acc[v].x)[q];
                    Hh.bb[q] = __float2bfloat16(val);
                    Ll.bb[q] = __float2bfloat16(val - __bfloat162float(Hh.bb[q]));
                }
                ((uint2*)(Ohi + (size_t)node * D))[lane + 32 * v] = Hh.u;
                ((uint2*)(Olo + (size_t)node * D))[lane + 32 * v] = Ll.u;
            } else {
                ((float4*)(OUT + (size_t)node * D))[lane + 32 * v] = acc[v];
            }
            if (STATS) {
                #pragma unroll
                for (int q = 0; q < 4; q++) {
                    float val = (&acc[v].x)[q];
                    stS[v][q] += val;
                    stQ[v][q] += val * val;
                }
            }
        }
    }
    if (STATS) {
        #pragma unroll
        for (int v = 0; v < NV; v++)
            #pragma unroll
            for (int q = 0; q < 4; q++) {
                atomicAdd(&sS[4 * lane + 128 * v + q], stS[v][q]);
                atomicAdd(&sQ[4 * lane + 128 * v + q], stQ[v][q]);
            }
        __syncthreads();
        for (int i = tid; i < D; i += 256) {
            atomicAdd(&pS[i], sS[i]);
            atomicAdd(&pQ[i], sQ[i]);
        }
    }
}

// ---------------------------------------------------------------------------
// HMMA bf16 hi/lo split GEMM, pass-fused: C = A @ W.
// CTA 128x128, 256 thr (2Mx4N warps, warp tile 64x32), 2-stage double buffer,
// TWO CTAs per SM. Per K-chunk(32): Ahi*Bhi + Alo*Bhi + Ahi*Blo.
// BNLOAD: A loaded as fp32 + BN(pSin/pQin)+ReLU+hi/lo split in the loader.
// STATS:  fused per-column sum/sumsq of C into pSout/pQout (layer 1).
// ---------------------------------------------------------------------------
#define PAD 40
#define TILE_B (128 * PAD * 2)          // 10240 B per tile (bf16)
#define STAGE_B (4 * TILE_B)            // Ahi,Alo,Bhi,Blo = 40960
#define GEMM_SMEM (2 * STAGE_B)         // 81920 B -> 2 CTAs/SM

template <int K, bool STATS, bool BNLOAD>
__global__ void __launch_bounds__(256, 2) mma_gemm_kernel(
    const __nv_bfloat16* __restrict__ Ahi, const __nv_bfloat16* __restrict__ Alo,
    const float* __restrict__ Afp, const float* __restrict__ gamma,
    const float* __restrict__ beta,
    const float* __restrict__ pSin, const float* __restrict__ pQin,
    float* __restrict__ pSout, float* __restrict__ pQout,
    const __nv_bfloat16* __restrict__ Bhi, const __nv_bfloat16* __restrict__ Blo,
    float* __restrict__ C, int Nc) {
    extern __shared__ char smem[];
    __shared__ float sS[128], sQ[128];
    __shared__ float sMuA[256], sScA[256], sBeA[256];
    const uint32_t sbase = smem_u32(smem);

    const int tid = threadIdx.x;
    const int warp = tid >> 5, lane = tid & 31;
    const int wm = warp >> 2, wn = warp & 3;  // 2x4 warps, warp tile 64x32
    const int m0 = blockIdx.y * 128;
    const int n0 = blockIdx.x * 128;

    if (STATS && tid < 128) { sS[tid] = 0.0f; sQ[tid] = 0.0f; }
    if (BNLOAD) {
        const float invn = 1.0f / (float)NN;
        for (int i = tid; i < K; i += 256) {
            float mu = pSin[i] * invn;
            float var = pQin[i] * invn - mu * mu;
            sMuA[i] = mu;
            sScA[i] = gamma[i] * rsqrtf(var + EPSV);
            sBeA[i] = beta[i];
        }
        __syncthreads();
    }

    float acc[4][4][4];
    #pragma unroll
    for (int i = 0; i < 4; i++)
        #pragma unroll
        for (int j = 0; j < 4; j++)
            #pragma unroll
            for (int q = 0; q < 4; q++) acc[i][j][q] = 0.0f;

    const int KC = K / 32;
    const int lrow = tid >> 2;   // 0..63 (rows lrow, lrow+64)
    const int lseg = tid & 3;

    auto issue = [&](int c) {
        const int p = c & 1;
        const int col0 = c * 32 + lseg * 8;
        #pragma unroll
        for (int h = 0; h < 2; h++) {
            int row = lrow + h * 64;
            const uint32_t off = (uint32_t)(p * STAGE_B) + (uint32_t)(row * PAD + lseg * 8) * 2;
            const uint32_t sb = sbase + off;
            int ra = m0 + row;
            bool ok = ra < NN;
            int rc = ok ? ra : 0;
            if (BNLOAD) {
                const float4* src = (const float4*)(Afp + (size_t)rc * K + col0);
                float4 v0 = src[0], v1 = src[1];
                float vv[8] = {v0.x, v0.y, v0.z, v0.w, v1.x, v1.y, v1.z, v1.w};
                union { __nv_bfloat16 b[8]; uint4 u; } Hh, Ll;
                #pragma unroll
                for (int q = 0; q < 8; q++) {
                    int cc = col0 + q;
                    float v = (vv[q] - sMuA[cc]) * sScA[cc] + sBeA[cc];
                    v = v > 0.0f ? v : 0.0f;
                    if (!ok) v = 0.0f;
                    Hh.b[q] = __float2bfloat16(v);
                    Ll.b[q] = __float2bfloat16(v - __bfloat162float(Hh.b[q]));
                }
                *(uint4*)(smem + off + 0 * TILE_B) = Hh.u;
                *(uint4*)(smem + off + 1 * TILE_B) = Ll.u;
            } else {
                cp16(sb + 0 * TILE_B, Ahi + (size_t)rc * K + col0, ok);
                cp16(sb + 1 * TILE_B, Alo + (size_t)rc * K + col0, ok);
            }
            cp16(sb + 2 * TILE_B, Bhi + (size_t)(n0 + row) * K + col0, true);
            cp16(sb + 3 * TILE_B, Blo + (size_t)(n0 + row) * K + col0, true);
        }
        cp_commit();
    };

    issue(0);
    if (KC > 1) issue(1); else cp_commit();

    const int jj = lane >> 3, rr = lane & 7;

    for (int c = 0; c < KC; c++) {
        if (c + 1 < KC) asm volatile("cp.async.wait_group 1;" ::: "memory");
        else            asm volatile("cp.async.wait_group 0;" ::: "memory");
        __syncthreads();   // stage c (cp.async + STS) visible to all warps

        const int p = c & 1;
        const uint32_t st = sbase + (uint32_t)(p * STAGE_B);

        #pragma unroll
        for (int ks = 0; ks < 2; ks++) {
            const int acol = ks * 16 + (jj >> 1) * 8;
            const int bcol = ks * 16 + (jj & 1) * 8;
            uint32_t ahi[4][4], alo[4][4], bhi[4][2];
            #pragma unroll
            for (int i = 0; i < 4; i++) {
                int row = wm * 64 + i * 16 + (jj & 1) * 8 + rr;
                uint32_t off = (uint32_t)(row * PAD + acol) * 2;
                LDSM_X4(ahi[i][0], ahi[i][1], ahi[i][2], ahi[i][3], st + 0 * TILE_B + off);
                LDSM_X4(alo[i][0], alo[i][1], alo[i][2], alo[i][3], st + 1 * TILE_B + off);
            }
            #pragma unroll
            for (int jt = 0; jt < 2; jt++) {
                int nrow = wn * 32 + jt * 16 + (jj >> 1) * 8 + rr;
                uint32_t off = (uint32_t)(nrow * PAD + bcol) * 2;
                LDSM_X4(bhi[jt * 2][0], bhi[jt * 2][1], bhi[jt * 2 + 1][0], bhi[jt * 2 + 1][1],
                        st + 2 * TILE_B + off);
            }
            #pragma unroll
            for (int i = 0; i < 4; i++)
                #pragma unroll
                for (int j = 0; j < 4; j++) {
                    MMA16816(acc[i][j], ahi[i], bhi[j]);
                    MMA16816(acc[i][j], alo[i], bhi[j]);
                }
            uint32_t blo[4][2];
            #pragma unroll
            for (int jt = 0; jt < 2; jt++) {
                int nrow = wn * 32 + jt * 16 + (jj >> 1) * 8 + rr;
                uint32_t off = (uint32_t)(nrow * PAD + bcol) * 2;
                LDSM_X4(blo[jt * 2][0], blo[jt * 2][1], blo[jt * 2 + 1][0], blo[jt * 2 + 1][1],
                        st + 3 * TILE_B + off);
            }
            #pragma unroll
            for (int i = 0; i < 4; i++)
                #pragma unroll
                for (int j = 0; j < 4; j++)
                    MMA16816(acc[i][j], ahi[i], blo[j]);
        }
        __syncthreads();   // all warps done with stage c before refill
        if (c + 2 < KC) issue(c + 2);
    }

    // Epilogue: C writes
    const int g = lane >> 2, t2 = (lane & 3) * 2;
    #pragma unroll
    for (int i = 0; i < 4; i++) {
        int row0 = m0 + wm * 64 + i * 16 + g;
        #pragma unroll
        for (int j = 0; j < 4; j++) {
            int col = n0 + wn * 32 + j * 8 + t2;
            if (row0 < NN)
                *(float2*)(C + (size_t)row0 * Nc + col) = make_float2(acc[i][j][0], acc[i][j][1]);
            if (row0 + 8 < NN)
                *(float2*)(C + (size_t)(row0 + 8) * Nc + col) = make_float2(acc[i][j][2], acc[i][j][3]);
        }
    }

    if (STATS) {
        // rows beyond NN were zero-filled in A -> contribute 0; no guard needed
        #pragma unroll
        for (int j = 0; j < 4; j++)
            #pragma unroll
            for (int qq = 0; qq < 2; qq++) {
                float s = 0.0f, q2 = 0.0f;
                #pragma unroll
                for (int i = 0; i < 4; i++) {
                    float a0 = acc[i][j][qq], a1 = acc[i][j][qq + 2];
                    s += a0 + a1;
                    q2 += a0 * a0 + a1 * a1;
                }
                #pragma unroll
                for (int off = 4; off < 32; off <<= 1) {
                    s  += __shfl_xor_sync(~0u, s, off);
                    q2 += __shfl_xor_sync(~0u, q2, off);
                }
                if (lane < 4) {
                    int col = wn * 32 + j * 8 + lane * 2 + qq;
                    atomicAdd(&sS[col], s);
                    atomicAdd(&sQ[col], q2);
                }
            }
        __syncthreads();
        if (tid < 128) {
            atomicAdd(&pSout[n0 + tid], sS[tid]);
            atomicAdd(&pQout[n0 + tid], sQ[tid]);
        }
    }
}

// ---------------------------------------------------------------------------
// Fused layer-3 BN+ReLU + head: OUT[N,10] = relu(BN(X)) @ Wout + bout.
// ---------------------------------------------------------------------------
__global__ void __launch_bounds__(256) bn_head_kernel(
    const float* __restrict__ X, const float* __restrict__ gamma,
    const float* __restrict__ beta, const float* __restrict__ W,
    const float* __restrict__ bias, float* __restrict__ OUT) {
    __shared__ float sW[128 * 10];
    __shared__ float sb[10];
    __shared__ float sMu[128], sSc[128], sBe[128];
    int tid = threadIdx.x;
    for (int i = tid; i < 1280; i += 256) sW[i] = W[i];
    if (tid < 10) sb[tid] = bias[tid];
    if (tid < 128) {
        const float invn = 1.0f / (float)NN;
        float mu = g_sum3[tid] * invn;
        float var = g_sumsq3[tid] * invn - mu * mu;
        sMu[tid] = mu;
        sSc[tid] = gamma[tid] * rsqrtf(var + EPSV);
        sBe[tid] = beta[tid];
    }
    __syncthreads();
    int warp = tid >> 5, lane = tid & 31;
    int row = blockIdx.x * 8 + warp;
    if (row >= NN) return;
    float4 x = *(const float4*)(X + (size_t)row * 128 + lane * 4);
    float y[4];
    #pragma unroll
    for (int q = 0; q < 4; q++) {
        int c = lane * 4 + q;
        float v = ((&x.x)[q] - sMu[c]) * sSc[c] + sBe[c];
        y[q] = v > 0.0f ? v : 0.0f;
    }
    #pragma unroll
    for (int c = 0; c < 10; c++) {
        float p = y[0] * sW[(lane * 4 + 0) * 10 + c] + y[1] * sW[(lane * 4 + 1) * 10 + c] +
                  y[2] * sW[(lane * 4 + 2) * 10 + c] + y[3] * sW[(lane * 4 + 3) * 10 + c];
        #pragma unroll
        for (int off = 16; off; off >>= 1) p += __shfl_xor_sync(0xffffffffu, p, off);
        if (lane == 0) OUT[(size_t)row * 10 + c] = p + sb[c];
    }
}

// ---------------------------------------------------------------------------
// Host-side orchestration
// ---------------------------------------------------------------------------
template <typename T>
static inline T* sym_addr(const void* sym) {
    void* p = nullptr;
    cudaGetSymbolAddress(&p, sym);
    return (T*)p;
}

extern "C" void kernel_launch(void* const* d_in, const int* in_sizes, int n_in,
                              void* d_out, int out_size) {
    const float* x   = (const float*)d_in[0];
    const void*  ei  = d_in[1];
    const float* W1  = (const float*)d_in[2];
    const float* g1  = (const float*)d_in[4];
    const float* be1 = (const float*)d_in[5];
    const float* W2  = (const float*)d_in[6];
    const float* g2  = (const float*)d_in[8];
    const float* be2 = (const float*)d_in[9];
    const float* W3  = (const float*)d_in[10];
    const float* g3  = (const float*)d_in[12];
    const float* be3 = (const float*)d_in[13];
    const float* Wo  = (const float*)d_in[14];
    const float* bo  = (const float*)d_in[15];
    float* out = (float*)d_out;

    float* H   = sym_addr<float>(g_H);
    float* H2  = sym_addr<float>(g_H2);
    float* AGG = sym_addr<float>(g_AGG);
    __nv_bfloat16* Ahi = sym_addr<__nv_bfloat16>(g_Ahi);
    __nv_bfloat16* Alo = sym_addr<__nv_bfloat16>(g_Alo);
    __nv_bfloat16* Bhi = sym_addr<__nv_bfloat16>(g_Bhi);
    __nv_bfloat16* Blo = sym_addr<__nv_bfloat16>(g_Blo);
    float* s1 = sym_addr<float>(g_sum1);
    float* q1 = sym_addr<float>(g_sumsq1);
    float* s2 = sym_addr<float>(g_sum2);
    float* q2 = sym_addr<float>(g_sumsq2);
    float* s3 = sym_addr<float>(g_sum3);
    float* q3 = sym_addr<float>(g_sumsq3);

    static int smem_set = 0;
    if (!smem_set) {
        cudaFuncSetAttribute(mma_gemm_kernel<128, true, false>, cudaFuncAttributeMaxDynamicSharedMemorySize, GEMM_SMEM);
        cudaFuncSetAttribute(mma_gemm_kernel<256, false, true>, cudaFuncAttributeMaxDynamicSharedMemorySize, GEMM_SMEM);
        smem_set = 1;
    }

    const int TB = 256;
    const int MT = (NN + 127) / 128;  // 782 M-tiles
    const int GAB = 1480;             // gather blocks (148 SMs x 10, grid-stride)

    // ---- graph prep: CSR by dst (cursor-atomic fill; REDG counting) ----
    init_kernel<<<(NN + TB - 1) / TB, TB>>>(ei);
    prep_edges_kernel<<<EDGE_NB + 512, TB>>>(ei, W1, W2, W3);  // + folded weight prep
    scan_local_kernel<<<SCAN_NB, 1024>>>();
    scan_add_kernel<<<(NN + TB - 1) / TB, TB>>>();             // tops prefix inline
    fill_kernel<<<(EE + TB - 1) / TB, TB>>>();

    // ---- layer 1: aggregate x (128, emit bf16) -> GEMM(+stats1) -> H ----
    gather_agg_kernel<128, true, false><<<GAB, 256>>>(x, nullptr, Ahi, Alo, nullptr, nullptr);
    mma_gemm_kernel<128, true, false><<<dim3(2, MT), 256, GEMM_SMEM>>>(
        Ahi, Alo, nullptr, nullptr, nullptr, nullptr, nullptr, s1, q1,
        Bhi + 0 * 65536, Blo + 0 * 65536, H, 256);

    // ---- layer 2: GEMM(BN1(H) fused) -> H2; gather(+stats2) -> AGG ----
    mma_gemm_kernel<256, false, true><<<dim3(2, MT), 256, GEMM_SMEM>>>(
        nullptr, nullptr, H, g1, be1, s1, q1, nullptr, nullptr,
        Bhi + 1 * 65536, Blo + 1 * 65536, H2, 256);
    gather_agg_kernel<256, false, true><<<GAB, 256>>>(H2, AGG, nullptr, nullptr, s2, q2);

    // ---- layer 3: GEMM(BN2(AGG) fused) -> H (128); gather(+stats3) -> H2 ----
    mma_gemm_kernel<256, false, true><<<dim3(1, MT), 256, GEMM_SMEM>>>(
        nullptr, nullptr, AGG, g2, be2, s2, q2, nullptr, nullptr,
        Bhi + 2 * 65536, Blo + 2 * 65536, H, 128);
    gather_agg_kernel<128, false, true><<<GAB, 256>>>(H, H2, nullptr, nullptr, s3, q3);

    // ---- head: relu(BN3(H2)) @ Wout + bout ----
    bn_head_kernel<<<(NN + 7) / 8, 256>>>(H2, g3, be3, Wo, bo, out);
}

// round 17
// speedup vs baseline: 1.4276x; 1.0197x over previous
#include <cuda_runtime.h>
#include <cuda_bf16.h>
#include <cstdint>

// Problem constants
#define NN 100000
#define EE 1600000
#define EPSV 1e-5f
#define SCAN_NB 98     // ceil(100000 / 1024)
#define EDGE_NB 6250   // prep_edges blocks

// ---------------------------------------------------------------------------
// Scratch (device globals; no runtime allocation allowed)
// ---------------------------------------------------------------------------
__device__ __align__(16) float g_H[(size_t)NN * 256];    // fp32 buffer A
__device__ __align__(16) float g_H2[(size_t)NN * 256];   // fp32 buffer B
__device__ __align__(16) float g_AGG[(size_t)NN * 256];  // fp32 buffer C
__device__ __align__(16) __nv_bfloat16 g_Ahi[(size_t)NN * 256]; // bf16 hi (layer-1 A)
__device__ __align__(16) __nv_bfloat16 g_Alo[(size_t)NN * 256]; // bf16 lo (layer-1 A)
__device__ __align__(16) __nv_bfloat16 g_Bhi[3][256 * 256];     // W^T hi per layer
__device__ __align__(16) __nv_bfloat16 g_Blo[3][256 * 256];     // W^T lo per layer
__device__ int   g_cnt[NN];      // in-degree (edges only)
__device__ int   g_off[NN + 1];  // CSR offsets (by dst)
__device__ int   g_cur[NN];      // fill cursors
__device__ int   g_blocksum[SCAN_NB];
__device__ int   g_src[EE];
__device__ int   g_dst[EE];
__device__ __align__(8) int2 g_edge[EE];   // dst-sorted (src, norm-bits)
__device__ float g_sum1[256], g_sumsq1[256];   // layer-1 stats (gemm1 -> gemm2)
__device__ float g_sum2[256], g_sumsq2[256];   // layer-2 stats (gather2 -> gemm3)
__device__ float g_sum3[128], g_sumsq3[128];   // layer-3 stats (gather3 -> head)
__device__ int   g_is32;

// ---------------------------------------------------------------------------
// Helpers
// ---------------------------------------------------------------------------
__device__ __forceinline__ uint32_t smem_u32(const void* p) {
    uint32_t a;
    asm("{ .reg .u64 t; cvta.to.shared.u64 t, %1; cvt.u32.u64 %0, t; }" : "=r"(a) : "l"(p));
    return a;
}

__device__ __forceinline__ void cp16(uint32_t dst, const void* src, bool pred) {
    int sz = pred ? 16 : 0;
    asm volatile("cp.async.cg.shared.global [%0], [%1], 16, %2;"
                 :: "r"(dst), "l"(src), "r"(sz) : "memory");
}
__device__ __forceinline__ void cp_commit() {
    asm volatile("cp.async.commit_group;" ::: "memory");
}

#define LDSM_X4(r0, r1, r2, r3, addr) \
    asm volatile("ldmatrix.sync.aligned.m8n8.x4.shared.b16 {%0,%1,%2,%3}, [%4];" \
                 : "=r"(r0), "=r"(r1), "=r"(r2), "=r"(r3) : "r"(addr))

#define MMA16816(d, a, b) \
    asm volatile("mma.sync.aligned.m16n8k16.row.col.f32.bf16.bf16.f32 " \
                 "{%0,%1,%2,%3}, {%4,%5,%6,%7}, {%8,%9}, {%0,%1,%2,%3};" \
                 : "+f"((d)[0]), "+f"((d)[1]), "+f"((d)[2]), "+f"((d)[3]) \
                 : "r"((a)[0]), "r"((a)[1]), "r"((a)[2]), "r"((a)[3]), \
                   "r"((b)[0]), "r"((b)[1]))

// ---------------------------------------------------------------------------
// init: zero counts, zero ALL stats buffers, detect edge dtype
// ---------------------------------------------------------------------------
__global__ void init_kernel(const void* p) {
    int i = blockIdx.x * blockDim.x + threadIdx.x;
    if (i < NN) g_cnt[i] = 0;
    if (i < 256) {
        g_sum1[i] = 0.0f; g_sumsq1[i] = 0.0f;
        g_sum2[i] = 0.0f; g_sumsq2[i] = 0.0f;
        if (i < 128) { g_sum3[i] = 0.0f; g_sumsq3[i] = 0.0f; }
    }
    if (i == 0) {
        const long long* q = (const long long*)p;
        int bad = 0;
        for (int k = 0; k < 256; k++) {
            long long v = q[k];
            if (v < 0 || v >= NN) bad = 1;
        }
        g_is32 = bad;
    }
}

// ---------------------------------------------------------------------------
// prep_edges (+ folded weight prep in trailing blocks).
// NOTE: atomic result is DISCARDED -> compiles to REDG (fire-and-forget).
// ---------------------------------------------------------------------------
__global__ void prep_edges_kernel(const void* p,
                                  const float* __restrict__ W1,
                                  const float* __restrict__ W2,
                                  const float* __restrict__ W3) {
    int b = blockIdx.x;
    if (b < EDGE_NB) {
        int e = b * 256 + threadIdx.x;
        if (e >= EE) return;
        int s, d;
        if (g_is32) {
            const int* q = (const int*)p;
            s = q[e]; d = q[EE + e];
        } else {
            const long long* q = (const long long*)p;
            s = (int)q[e]; d = (int)q[EE + e];
        }
        g_src[e] = s;
        g_dst[e] = d;
        atomicAdd(&g_cnt[d], 1);
    } else {
        int idx = (b - EDGE_NB) * 256 + threadIdx.x;  // 0..131071 exactly
        const float* W; int K, Nc, l;
        if (idx < 32768)       { W = W1; K = 128; Nc = 256; l = 0; }
        else if (idx < 98304)  { W = W2; K = 256; Nc = 256; l = 1; idx -= 32768; }
        else                   { W = W3; K = 256; Nc = 128; l = 2; idx -= 98304; }
        int k = idx / Nc, n = idx - k * Nc;
        float v = W[idx];
        __nv_bfloat16 h = __float2bfloat16(v);
        g_Bhi[l][n * K + k] = h;
        g_Blo[l][n * K + k] = __float2bfloat16(v - __bfloat162float(h));
    }
}

// Phase 1: per-block (1024 elems) exclusive scan -> g_off (local), total -> g_blocksum
__global__ void __launch_bounds__(1024) scan_local_kernel() {
    __shared__ int wsum[32];
    int tid = threadIdx.x, lane = tid & 31, w = tid >> 5;
    int i = blockIdx.x * 1024 + tid;
    int v = (i < NN) ? g_cnt[i] : 0;
    int x = v;
    #pragma unroll
    for (int o = 1; o < 32; o <<= 1) { int y = __shfl_up_sync(~0u, x, o); if (lane >= o) x += y; }
    if (lane == 31) wsum[w] = x;
    __syncthreads();
    if (w == 0) {
        int s = wsum[lane];
        #pragma unroll
        for (int o = 1; o < 32; o <<= 1) { int y = __shfl_up_sync(~0u, s, o); if (lane >= o) s += y; }
        wsum[lane] = s;
    }
    __syncthreads();
    int wpre = (w == 0) ? 0 : wsum[w - 1];
    if (i < NN) g_off[i] = wpre + (x - v);   // block-local exclusive scan
    if (tid == 1023) g_blocksum[blockIdx.x] = wpre + x;
}

// Phase 2+3 fused: each block computes its chunk's blocksum prefix inline,
// adds it, inits cursors, sets sentinel.
__global__ void __launch_bounds__(256) scan_add_kernel() {
    __shared__ int spre;
    const int tid = threadIdx.x, lane = tid & 31;
    const int chunk = blockIdx.x >> 2;  // 4 blocks of 256 per 1024-chunk
    if (tid < 32) {
        int s = 0;
        for (int j = lane; j < chunk; j += 32) s += g_blocksum[j];
        #pragma unroll
        for (int o = 16; o; o >>= 1) s += __shfl_xor_sync(~0u, s, o);
        if (lane == 0) spre = s;
    }
    __syncthreads();
    int i = blockIdx.x * 256 + tid;
    if (i < NN) {
        int o = g_off[i] + spre;
        g_off[i] = o;
        g_cur[i] = o;
    }
    if (i == 0) g_off[NN] = EE;
}

__global__ void fill_kernel() {
    int e = blockIdx.x * blockDim.x + threadIdx.x;
    if (e >= EE) return;
    int s = g_src[e], d = g_dst[e];
    int pos = atomicAdd(&g_cur[d], 1);
    float nrm = rsqrtf((float)(g_cnt[s] + 1)) * rsqrtf((float)(g_cnt[d] + 1));
    g_edge[pos] = make_int2(s, __float_as_int(nrm));
}

// ---------------------------------------------------------------------------
// CSR gather-aggregate: one warp per node, NV=D/128 float4 vectors per lane;
// 8-edge unroll when NV==1, 4-edge otherwise. int2 edge metadata.
// EMIT_BF: write bf16 hi/lo instead of fp32 (layer-1 A operand).
// STATS:   per-column sum/sumsq into pS/pQ (block-reduce + atomicAdd).
// ---------------------------------------------------------------------------
template <int D, bool EMIT_BF, bool STATS>
__global__ void __launch_bounds__(256) gather_agg_kernel(
    const float* __restrict__ H, float* __restrict__ OUT,
    __nv_bfloat16* __restrict__ Ohi, __nv_bfloat16* __restrict__ Olo,
    float* __restrict__ pS, float* __restrict__ pQ) {
    __shared__ float sS[D], sQ[D];
    const int NV = D / 128;
    const int tid = threadIdx.x;
    const int w = tid >> 5, lane = tid & 31;
    if (STATS) {
        if (tid < D) { sS[tid] = 0.0f; sQ[tid] = 0.0f; }
        __syncthreads();
    }
    float stS[NV][4], stQ[NV][4];
    #pragma unroll
    for (int v = 0; v < NV; v++)
        #pragma unroll
        for (int q = 0; q < 4; q++) { stS[v][q] = 0.0f; stQ[v][q] = 0.0f; }
    const int2* __restrict__ E = g_edge;

    for (int node = blockIdx.x * 8 + w; node < NN; node += gridDim.x * 8) {
        float4 acc[NV];
        float selfw = 1.0f / (float)(g_cnt[node] + 1);
        #pragma unroll
        for (int v = 0; v < NV; v++) {
            float4 h = ((const float4*)(H + (size_t)node * D))[lane + 32 * v];
            acc[v] = make_float4(h.x * selfw, h.y * selfw, h.z * selfw, h.w * selfw);
        }
        int j = g_off[node], jend = g_off[node + 1];
        if (NV == 1) {
            for (; j + 8 <= jend; j += 8) {
                int2 m[8];
                #pragma unroll
                for (int k = 0; k < 8; k++) m[k] = E[j + k];
                float4 h[8];
                #pragma unroll
                for (int k = 0; k < 8; k++)
                    h[k] = ((const float4*)(H + (size_t)m[k].x * D))[lane];
                #pragma unroll
                for (int k = 0; k < 8; k++) {
                    float wt = __int_as_float(m[k].y);
                    acc[0].x += wt * h[k].x; acc[0].y += wt * h[k].y;
                    acc[0].z += wt * h[k].z; acc[0].w += wt * h[k].w;
                }
            }
        }
        for (; j + 4 <= jend; j += 4) {
            int2 m0 = E[j], m1 = E[j + 1], m2 = E[j + 2], m3 = E[j + 3];
            float w0 = __int_as_float(m0.y), w1 = __int_as_float(m1.y);
            float w2 = __int_as_float(m2.y), w3 = __int_as_float(m3.y);
            #pragma unroll
            for (int v = 0; v < NV; v++) {
                float4 h0 = ((const float4*)(H + (size_t)m0.x * D))[lane + 32 * v];
                float4 h1 = ((const float4*)(H + (size_t)m1.x * D))[lane + 32 * v];
                float4 h2 = ((const float4*)(H + (size_t)m2.x * D))[lane + 32 * v];
                float4 h3 = ((const float4*)(H + (size_t)m3.x * D))[lane + 32 * v];
                acc[v].x += w0 * h0.x + w1 * h1.x + w2 * h2.x + w3 * h3.x;
                acc[v].y += w0 * h0.y + w1 * h1.y + w2 * h2.y + w3 * h3.y;
                acc[v].z += w0 * h0.z + w1 * h1.z + w2 * h2.z + w3 * h3.z;
                acc[v].w += w0 * h0.w + w1 * h1.w + w2 * h2.w + w3 * h3.w;
            }
        }
        for (; j < jend; j++) {
            int2 m = E[j];
            float wt = __int_as_float(m.y);
            #pragma unroll
            for (int v = 0; v < NV; v++) {
                float4 h = ((const float4*)(H + (size_t)m.x * D))[lane + 32 * v];
                acc[v].x += wt * h.x; acc[v].y += wt * h.y;
                acc[v].z += wt * h.z; acc[v].w += wt * h.w;
            }
        }
        #pragma unroll
        for (int v = 0; v < NV; v++) {
            if (EMIT_BF) {
                union { __nv_bfloat16 bb[4]; uint2 u; } Hh, Ll;
                #pragma unroll
                for (int q = 0; q < 4; q++) {
                    float val = (&acc[v].x)[q];
                    Hh.bb[q] = __float2bfloat16(val);
                    Ll.bb[q] = __float2bfloat16(val - __bfloat162float(Hh.bb[q]));
                }
                ((uint2*)(Ohi + (size_t)node * D))[lane + 32 * v] = Hh.u;
                ((uint2*)(Olo + (size_t)node * D))[lane + 32 * v] = Ll.u;
            } else {
                ((float4*)(OUT + (size_t)node * D))[lane + 32 * v] = acc[v];
            }
            if (STATS) {
                #pragma unroll
                for (int q = 0; q < 4; q++) {
                    float val = (&acc[v].x)[q];
                    stS[v][q] += val;
                    stQ[v][q] += val * val;
                }
            }
        }
    }
    if (STATS) {
        #pragma unroll
        for (int v = 0; v < NV; v++)
            #pragma unroll
            for (int q = 0; q < 4; q++) {
                atomicAdd(&sS[4 * lane + 128 * v + q], stS[v][q]);
                atomicAdd(&sQ[4 * lane + 128 * v + q], stQ[v][q]);
            }
        __syncthreads();
        for (int i = tid; i < D; i += 256) {
            atomicAdd(&pS[i], sS[i]);
            atomicAdd(&pQ[i], sQ[i]);
        }
    }
}

// ---------------------------------------------------------------------------
// HMMA bf16 hi/lo split GEMM, pass-fused: C = A @ W.
// CTA 128x128, 256 thr (2Mx4N warps, warp tile 64x32), 2-stage double buffer,
// TWO CTAs per SM. Per K-chunk(32): Ahi*Bhi + Alo*Bhi + Ahi*Blo.
// BNLOAD: A loaded as fp32 + BN(pSin/pQin)+ReLU+hi/lo split in the loader.
// STATS:  fused per-column sum/sumsq of C into pSout/pQout (layer 1).
// ---------------------------------------------------------------------------
#define PAD 40
#define TILE_B (128 * PAD * 2)          // 10240 B per tile (bf16)
#define STAGE_B (4 * TILE_B)            // Ahi,Alo,Bhi,Blo = 40960
#define GEMM_SMEM (2 * STAGE_B)         // 81920 B -> 2 CTAs/SM

template <int K, bool STATS, bool BNLOAD>
__global__ void __launch_bounds__(256, 2) mma_gemm_kernel(
    const __nv_bfloat16* __restrict__ Ahi, const __nv_bfloat16* __restrict__ Alo,
    const float* __restrict__ Afp, const float* __restrict__ gamma,
    const float* __restrict__ beta,
    const float* __restrict__ pSin, const float* __restrict__ pQin,
    float* __restrict__ pSout, float* __restrict__ pQout,
    const __nv_bfloat16* __restrict__ Bhi, const __nv_bfloat16* __restrict__ Blo,
    float* __restrict__ C, int Nc) {
    extern __shared__ char smem[];
    __shared__ float sS[128], sQ[128];
    __shared__ float sMuA[256], sScA[256], sBeA[256];
    const uint32_t sbase = smem_u32(smem);

    const int tid = threadIdx.x;
    const int warp = tid >> 5, lane = tid & 31;
    const int wm = warp >> 2, wn = warp & 3;  // 2x4 warps, warp tile 64x32
    const int m0 = blockIdx.y * 128;
    const int n0 = blockIdx.x * 128;

    if (STATS && tid < 128) { sS[tid] = 0.0f; sQ[tid] = 0.0f; }
    if (BNLOAD) {
        const float invn = 1.0f / (float)NN;
        for (int i = tid; i < K; i += 256) {
            float mu = pSin[i] * invn;
            float var = pQin[i] * invn - mu * mu;
            sMuA[i] = mu;
            sScA[i] = gamma[i] * rsqrtf(var + EPSV);
            sBeA[i] = beta[i];
        }
        __syncthreads();
    }

    float acc[4][4][4];
    #pragma unroll
    for (int i = 0; i < 4; i++)
        #pragma unroll
        for (int j = 0; j < 4; j++)
            #pragma unroll
            for (int q = 0; q < 4; q++) acc[i][j][q] = 0.0f;

    const int KC = K / 32;
    const int lrow = tid >> 2;   // 0..63 (rows lrow, lrow+64)
    const int lseg = tid & 3;

    auto issue = [&](int c) {
        const int p = c & 1;
        const int col0 = c * 32 + lseg * 8;
        #pragma unroll
        for (int h = 0; h < 2; h++) {
            int row = lrow + h * 64;
            const uint32_t off = (uint32_t)(p * STAGE_B) + (uint32_t)(row * PAD + lseg * 8) * 2;
            const uint32_t sb = sbase + off;
            int ra = m0 + row;
            bool ok = ra < NN;
            int rc = ok ? ra : 0;
            if (BNLOAD) {
                const float4* src = (const float4*)(Afp + (size_t)rc * K + col0);
                float4 v0 = src[0], v1 = src[1];
                float vv[8] = {v0.x, v0.y, v0.z, v0.w, v1.x, v1.y, v1.z, v1.w};
                union { __nv_bfloat16 b[8]; uint4 u; } Hh, Ll;
                #pragma unroll
                for (int q = 0; q < 8; q++) {
                    int cc = col0 + q;
                    float v = (vv[q] - sMuA[cc]) * sScA[cc] + sBeA[cc];
                    v = v > 0.0f ? v : 0.0f;
                    if (!ok) v = 0.0f;
                    Hh.b[q] = __float2bfloat16(v);
                    Ll.b[q] = __float2bfloat16(v - __bfloat162float(Hh.b[q]));
                }
                *(uint4*)(smem + off + 0 * TILE_B) = Hh.u;
                *(uint4*)(smem + off + 1 * TILE_B) = Ll.u;
            } else {
                cp16(sb + 0 * TILE_B, Ahi + (size_t)rc * K + col0, ok);
                cp16(sb + 1 * TILE_B, Alo + (size_t)rc * K + col0, ok);
            }
            cp16(sb + 2 * TILE_B, Bhi + (size_t)(n0 + row) * K + col0, true);
            cp16(sb + 3 * TILE_B, Blo + (size_t)(n0 + row) * K + col0, true);
        }
        cp_commit();
    };

    issue(0);
    if (KC > 1) issue(1); else cp_commit();

    const int jj = lane >> 3, rr = lane & 7;

    for (int c = 0; c < KC; c++) {
        if (c + 1 < KC) asm volatile("cp.async.wait_group 1;" ::: "memory");
        else            asm volatile("cp.async.wait_group 0;" ::: "memory");
        __syncthreads();   // stage c (cp.async + STS) visible to all warps

        const int p = c & 1;
        const uint32_t st = sbase + (uint32_t)(p * STAGE_B);

        #pragma unroll
        for (int ks = 0; ks < 2; ks++) {
            const int acol = ks * 16 + (jj >> 1) * 8;
            const int bcol = ks * 16 + (jj & 1) * 8;
            uint32_t ahi[4][4], alo[4][4], bhi[4][2];
            #pragma unroll
            for (int i = 0; i < 4; i++) {
                int row = wm * 64 + i * 16 + (jj & 1) * 8 + rr;
                uint32_t off = (uint32_t)(row * PAD + acol) * 2;
                LDSM_X4(ahi[i][0], ahi[i][1], ahi[i][2], ahi[i][3], st + 0 * TILE_B + off);
                LDSM_X4(alo[i][0], alo[i][1], alo[i][2], alo[i][3], st + 1 * TILE_B + off);
            }
            #pragma unroll
            for (int jt = 0; jt < 2; jt++) {
                int nrow = wn * 32 + jt * 16 + (jj >> 1) * 8 + rr;
                uint32_t off = (uint32_t)(nrow * PAD + bcol) * 2;
                LDSM_X4(bhi[jt * 2][0], bhi[jt * 2][1], bhi[jt * 2 + 1][0], bhi[jt * 2 + 1][1],
                        st + 2 * TILE_B + off);
            }
            #pragma unroll
            for (int i = 0; i < 4; i++)
                #pragma unroll
                for (int j = 0; j < 4; j++) {
                    MMA16816(acc[i][j], ahi[i], bhi[j]);
                    MMA16816(acc[i][j], alo[i], bhi[j]);
                }
            uint32_t blo[4][2];
            #pragma unroll
            for (int jt = 0; jt < 2; jt++) {
                int nrow = wn * 32 + jt * 16 + (jj >> 1) * 8 + rr;
                uint32_t off = (uint32_t)(nrow * PAD + bcol) * 2;
                LDSM_X4(blo[jt * 2][0], blo[jt * 2][1], blo[jt * 2 + 1][0], blo[jt * 2 + 1][1],
                        st + 3 * TILE_B + off);
            }
            #pragma unroll
            for (int i = 0; i < 4; i++)
                #pragma unroll
                for (int j = 0; j < 4; j++)
                    MMA16816(acc[i][j], ahi[i], blo[j]);
        }
        __syncthreads();   // all warps done with stage c before refill
        if (c + 2 < KC) issue(c + 2);
    }

    // Epilogue: C writes
    const int g = lane >> 2, t2 = (lane & 3) * 2;
    #pragma unroll
    for (int i = 0; i < 4; i++) {
        int row0 = m0 + wm * 64 + i * 16 + g;
        #pragma unroll
        for (int j = 0; j < 4; j++) {
            int col = n0 + wn * 32 + j * 8 + t2;
            if (row0 < NN)
                *(float2*)(C + (size_t)row0 * Nc + col) = make_float2(acc[i][j][0], acc[i][j][1]);
            if (row0 + 8 < NN)
                *(float2*)(C + (size_t)(row0 + 8) * Nc + col) = make_float2(acc[i][j][2], acc[i][j][3]);
        }
    }

    if (STATS) {
        // rows beyond NN were zero-filled in A -> contribute 0; no guard needed
        #pragma unroll
        for (int j = 0; j < 4; j++)
            #pragma unroll
            for (int qq = 0; qq < 2; qq++) {
                float s = 0.0f, q2 = 0.0f;
                #pragma unroll
                for (int i = 0; i < 4; i++) {
                    float a0 = acc[i][j][qq], a1 = acc[i][j][qq + 2];
                    s += a0 + a1;
                    q2 += a0 * a0 + a1 * a1;
                }
                #pragma unroll
                for (int off = 4; off < 32; off <<= 1) {
                    s  += __shfl_xor_sync(~0u, s, off);
                    q2 += __shfl_xor_sync(~0u, q2, off);
                }
                if (lane < 4) {
                    int col = wn * 32 + j * 8 + lane * 2 + qq;
                    atomicAdd(&sS[col], s);
                    atomicAdd(&sQ[col], q2);
                }
            }
        __syncthreads();
        if (tid < 128) {
            atomicAdd(&pSout[n0 + tid], sS[tid]);
            atomicAdd(&pQout[n0 + tid], sQ[tid]);
        }
    }
}

// ---------------------------------------------------------------------------
// Fused layer-3 BN+ReLU + head: OUT[N,10] = relu(BN(X)) @ Wout + bout.
// Grid-stride persistent blocks: smem staging amortized over many rows.
// ---------------------------------------------------------------------------
__global__ void __launch_bounds__(256) bn_head_kernel(
    const float* __restrict__ X, const float* __restrict__ gamma,
    const float* __restrict__ beta, const float* __restrict__ W,
    const float* __restrict__ bias, float* __restrict__ OUT) {
    __shared__ float sW[128 * 10];
    __shared__ float sb[10];
    __shared__ float sMu[128], sSc[128], sBe[128];
    int tid = threadIdx.x;
    for (int i = tid; i < 1280; i += 256) sW[i] = W[i];
    if (tid < 10) sb[tid] = bias[tid];
    if (tid < 128) {
        const float invn = 1.0f / (float)NN;
        float mu = g_sum3[tid] * invn;
        float var = g_sumsq3[tid] * invn - mu * mu;
        sMu[tid] = mu;
        sSc[tid] = gamma[tid] * rsqrtf(var + EPSV);
        sBe[tid] = beta[tid];
    }
    __syncthreads();
    int warp = tid >> 5, lane = tid & 31;
    for (int row = blockIdx.x * 8 + warp; row < NN; row += gridDim.x * 8) {
        float4 x = *(const float4*)(X + (size_t)row * 128 + lane * 4);
        float y[4];
        #pragma unroll
        for (int q = 0; q < 4; q++) {
            int c = lane * 4 + q;
            float v = ((&x.x)[q] - sMu[c]) * sSc[c] + sBe[c];
            y[q] = v > 0.0f ? v : 0.0f;
        }
        #pragma unroll
        for (int c = 0; c < 10; c++) {
            float p = y[0] * sW[(lane * 4 + 0) * 10 + c] + y[1] * sW[(lane * 4 + 1) * 10 + c] +
                      y[2] * sW[(lane * 4 + 2) * 10 + c] + y[3] * sW[(lane * 4 + 3) * 10 + c];
            #pragma unroll
            for (int off = 16; off; off >>= 1) p += __shfl_xor_sync(0xffffffffu, p, off);
            if (lane == 0) OUT[(size_t)row * 10 + c] = p + sb[c];
        }
    }
}

// ---------------------------------------------------------------------------
// Host-side orchestration
// ---------------------------------------------------------------------------
template <typename T>
static inline T* sym_addr(const void* sym) {
    void* p = nullptr;
    cudaGetSymbolAddress(&p, sym);
    return (T*)p;
}

extern "C" void kernel_launch(void* const* d_in, const int* in_sizes, int n_in,
                              void* d_out, int out_size) {
    const float* x   = (const float*)d_in[0];
    const void*  ei  = d_in[1];
    const float* W1  = (const float*)d_in[2];
    const float* g1  = (const float*)d_in[4];
    const float* be1 = (const float*)d_in[5];
    const float* W2  = (const float*)d_in[6];
    const float* g2  = (const float*)d_in[8];
    const float* be2 = (const float*)d_in[9];
    const float* W3  = (const float*)d_in[10];
    const float* g3  = (const float*)d_in[12];
    const float* be3 = (const float*)d_in[13];
    const float* Wo  = (const float*)d_in[14];
    const float* bo  = (const float*)d_in[15];
    float* out = (float*)d_out;

    float* H   = sym_addr<float>(g_H);
    float* H2  = sym_addr<float>(g_H2);
    float* AGG = sym_addr<float>(g_AGG);
    __nv_bfloat16* Ahi = sym_addr<__nv_bfloat16>(g_Ahi);
    __nv_bfloat16* Alo = sym_addr<__nv_bfloat16>(g_Alo);
    __nv_bfloat16* Bhi = sym_addr<__nv_bfloat16>(g_Bhi);
    __nv_bfloat16* Blo = sym_addr<__nv_bfloat16>(g_Blo);
    float* s1 = sym_addr<float>(g_sum1);
    float* q1 = sym_addr<float>(g_sumsq1);
    float* s2 = sym_addr<float>(g_sum2);
    float* q2 = sym_addr<float>(g_sumsq2);
    float* s3 = sym_addr<float>(g_sum3);
    float* q3 = sym_addr<float>(g_sumsq3);

    static int smem_set = 0;
    if (!smem_set) {
        cudaFuncSetAttribute(mma_gemm_kernel<128, true, false>, cudaFuncAttributeMaxDynamicSharedMemorySize, GEMM_SMEM);
        cudaFuncSetAttribute(mma_gemm_kernel<256, false, true>, cudaFuncAttributeMaxDynamicSharedMemorySize, GEMM_SMEM);
        smem_set = 1;
    }

    const int TB = 256;
    const int MT = (NN + 127) / 128;  // 782 M-tiles
    const int GAB = 1184;             // gather blocks (148 SMs x 8) — best known

    // ---- graph prep: CSR by dst (cursor-atomic fill; REDG counting) ----
    init_kernel<<<(NN + TB - 1) / TB, TB>>>(ei);
    prep_edges_kernel<<<EDGE_NB + 512, TB>>>(ei, W1, W2, W3);  // + folded weight prep
    scan_local_kernel<<<SCAN_NB, 1024>>>();
    scan_add_kernel<<<(NN + TB - 1) / TB, TB>>>();             // tops prefix inline
    fill_kernel<<<(EE + TB - 1) / TB, TB>>>();

    // ---- layer 1: aggregate x (128, emit bf16) -> GEMM(+stats1) -> H ----
    gather_agg_kernel<128, true, false><<<GAB, 256>>>(x, nullptr, Ahi, Alo, nullptr, nullptr);
    mma_gemm_kernel<128, true, false><<<dim3(2, MT), 256, GEMM_SMEM>>>(
        Ahi, Alo, nullptr, nullptr, nullptr, nullptr, nullptr, s1, q1,
        Bhi + 0 * 65536, Blo + 0 * 65536, H, 256);

    // ---- layer 2: GEMM(BN1(H) fused) -> H2; gather(+stats2) -> AGG ----
    mma_gemm_kernel<256, false, true><<<dim3(2, MT), 256, GEMM_SMEM>>>(
        nullptr, nullptr, H, g1, be1, s1, q1, nullptr, nullptr,
        Bhi + 1 * 65536, Blo + 1 * 65536, H2, 256);
    gather_agg_kernel<256, false, true><<<GAB, 256>>>(H2, AGG, nullptr, nullptr, s2, q2);

    // ---- layer 3: GEMM(BN2(AGG) fused) -> H (128); gather(+stats3) -> H2 ----
    mma_gemm_kernel<256, false, true><<<dim3(1, MT), 256, GEMM_SMEM>>>(
        nullptr, nullptr, AGG, g2, be2, s2, q2, nullptr, nullptr,
        Bhi + 2 * 65536, Blo + 2 * 65536, H, 128);
    gather_agg_kernel<128, false, true><<<GAB, 256>>>(H, H2, nullptr, nullptr, s3, q3);

    // ---- head: relu(BN3(H2)) @ Wout + bout (persistent blocks) ----
    bn_head_kernel<<<GAB, 256>>>(H2, g3, be3, Wo, bo, out);
}